// round 6
// baseline (speedup 1.0000x reference)
#include <cuda_runtime.h>
#include <cuda_bf16.h>
#include <math.h>

#define BB 32
#define DD 8732
#define OO 8
#define CC 21
#define LL 32
#define KK 256
#define NCH 8
#define CH  1092   // NCH*CH = 8736 >= DD
#define NCE 35     // encce chunks per batch (35*256 >= 8732)

// ---------------- device scratch ----------------
__device__ unsigned char d_ct[BB*DD];      // conf (5 bits) | truth idx (3 bits)
__device__ float  d_ceneg[BB*DD];
__device__ unsigned long long d_bestkey[BB*NCH*OO]; // per (batch, chunk, truth)

// per-block partials (no global atomics anywhere)
__device__ double d_pll[BB*NCE], d_plp[BB*NCE], d_pce[BB*NCE];
__device__ int    d_npb[BB*NCE];
__device__ double d_topksum[BB];
__device__ double d_pdesk[KK], d_ptrips[KK];
__device__ int    d_pnpp[KK], d_pnnp[KK], d_ptc[KK];

__device__ float  d_emb[KK*LL];
__device__ int    d_lab[KK];
__device__ float  d_qp[KK*3];
__device__ int    d_val[KK];

// fast exp on the FMA pipe (inputs are x - max <= 0)
__device__ __forceinline__ float fexp(float x) {
    x = fmaxf(x, -80.0f);
    float y = x * 1.442695040888963f;
    float n = rintf(y);
    float f = y - n;                       // [-0.5, 0.5]
    float p = 1.54035303933816e-4f;
    p = fmaf(p, f, 1.33335581464284e-3f);
    p = fmaf(p, f, 9.61812910762848e-3f);
    p = fmaf(p, f, 5.55041086648216e-2f);
    p = fmaf(p, f, 2.40226506959101e-1f);
    p = fmaf(p, f, 6.93147180559945e-1f);
    p = fmaf(p, f, 1.0f);
    return __int_as_float(__float_as_int(p) + (((int)n) << 23));
}

// ---------------- kernels ----------------

// Per-truth best prior within this chunk; one plain store per (block, truth).
__global__ void k_match1(const float* __restrict__ dbox,
                         const float* __restrict__ tgt) {
    const int b = blockIdx.y;
    const int base = blockIdx.x * CH;
    const int tid = threadIdx.x;

    __shared__ float tx1[OO], ty1[OO], tx2[OO], ty2[OO], ta[OO];
    if (tid < OO) {
        const float* p = tgt + (size_t)(b*OO + tid)*9;
        tx1[tid] = p[0]; ty1[tid] = p[1]; tx2[tid] = p[2]; ty2[tid] = p[3];
        ta[tid]  = (p[2]-p[0])*(p[3]-p[1]);
    }
    __syncthreads();

    unsigned long long bk[OO];
#pragma unroll
    for (int t = 0; t < OO; t++) bk[t] = 0ull;

    int dend = base + CH; if (dend > DD) dend = DD;
    for (int d = base + tid; d < dend; d += 256) {
        float4 db = __ldg((const float4*)(dbox + d*4));
        float px1 = db.x - db.z*0.5f, py1 = db.y - db.w*0.5f;
        float px2 = db.x + db.z*0.5f, py2 = db.y + db.w*0.5f;
        float pa = (px2-px1)*(py2-py1);
#pragma unroll
        for (int t = 0; t < OO; t++) {
            float ix = fmaxf(fminf(tx2[t], px2) - fmaxf(tx1[t], px1), 0.0f);
            float iy = fmaxf(fminf(ty2[t], py2) - fmaxf(ty1[t], py1), 0.0f);
            float inter = ix * iy;
            float iou = inter / (ta[t] + pa - inter);
            unsigned long long key =
                ((unsigned long long)__float_as_uint(iou) << 32) |
                (unsigned long long)(0xFFFFFFFFu - (unsigned)d);
            if (key > bk[t]) bk[t] = key;
        }
    }

    __shared__ unsigned long long wk[8][OO];
    int wid = tid >> 5, lane = tid & 31;
#pragma unroll
    for (int t = 0; t < OO; t++) {
        unsigned long long k = bk[t];
#pragma unroll
        for (int s = 16; s > 0; s >>= 1) {
            unsigned long long o = __shfl_down_sync(0xffffffffu, k, s);
            if (o > k) k = o;
        }
        if (lane == 0) wk[wid][t] = k;
    }
    __syncthreads();
    if (tid < OO) {
        unsigned long long k = 0ull;
#pragma unroll
        for (int w = 0; w < 8; w++) if (wk[w][tid] > k) k = wk[w][tid];
        d_bestkey[(b*NCH + blockIdx.x)*OO + tid] = k;
    }
}

// Fused: recompute per-prior best truth, apply overrides, conf_t, encode,
// loc/pose losses, CE. Per-block partial sums (no atomics).
__global__ void k_encce(const float* __restrict__ loc,
                        const float* __restrict__ pose,
                        const float* __restrict__ dbox,
                        const float* __restrict__ tgt,
                        const float* __restrict__ conf) {
    const int b = blockIdx.y;
    const int tid = threadIdx.x;
    const int d = blockIdx.x * 256 + tid;

    __shared__ float tx1[OO], ty1[OO], tx2[OO], ty2[OO], ta[OO];
    __shared__ float tpz[OO][3];
    __shared__ int   tlab[OO], bestd[OO];
    __shared__ float sconf[256*CC];

    if (tid < OO) {
        const float* p = tgt + (size_t)(b*OO + tid)*9;
        tx1[tid] = p[0]; ty1[tid] = p[1]; tx2[tid] = p[2]; ty2[tid] = p[3];
        ta[tid]  = (p[2]-p[0])*(p[3]-p[1]);
        tlab[tid] = (int)p[4];
        tpz[tid][0] = p[5]; tpz[tid][1] = p[6]; tpz[tid][2] = p[7];
        unsigned long long k = 0ull;
#pragma unroll
        for (int c = 0; c < NCH; c++) {
            unsigned long long o = d_bestkey[(b*NCH + c)*OO + tid];
            if (o > k) k = o;
        }
        bestd[tid] = (int)(0xFFFFFFFFu - (unsigned)(k & 0xFFFFFFFFull));
    }
    {
        int d0 = blockIdx.x * 256;
        int nblk = DD - d0; if (nblk > 256) nblk = 256;
        const float* cbase = conf + ((size_t)b*DD + d0)*CC;
        for (int i = tid; i < nblk*CC; i += 256) sconf[i] = cbase[i];
    }
    __syncthreads();

    float ll = 0.0f, lp = 0.0f, cepos = 0.0f;
    int np = 0;
    if (d < DD) {
        int idx = b*DD + d;
        float4 db = __ldg((const float4*)(dbox + d*4));
        float px1 = db.x - db.z*0.5f, py1 = db.y - db.w*0.5f;
        float px2 = db.x + db.z*0.5f, py2 = db.y + db.w*0.5f;
        float pa = (px2-px1)*(py2-py1);
        float mv = -1.0f; int mt = 0;
#pragma unroll
        for (int t = 0; t < OO; t++) {
            float ix = fmaxf(fminf(tx2[t], px2) - fmaxf(tx1[t], px1), 0.0f);
            float iy = fmaxf(fminf(ty2[t], py2) - fmaxf(ty1[t], py1), 0.0f);
            float inter = ix * iy;
            float iou = inter / (ta[t] + pa - inter);
            if (iou > mv) { mv = iou; mt = t; }   // first occurrence over t
        }
#pragma unroll
        for (int t = 0; t < OO; t++) {            // overrides, last t wins
            if (bestd[t] == d) { mv = 2.0f; mt = t; }
        }
        int cf = (mv < 0.5f) ? 0 : (tlab[mt] + 1);
        d_ct[idx] = (unsigned char)(cf | (mt << 5));

        if (cf > 0) {
            np = 1;
            float g0 = ((tx1[mt] + tx2[mt])*0.5f - db.x) / (0.1f * db.z);
            float g1 = ((ty1[mt] + ty2[mt])*0.5f - db.y) / (0.1f * db.w);
            float g2 = logf((tx2[mt] - tx1[mt]) / db.z) / 0.2f;
            float g3 = logf((ty2[mt] - ty1[mt]) / db.w) / 0.2f;
            float g[4] = {g0, g1, g2, g3};
#pragma unroll
            for (int i = 0; i < 4; i++) {
                float dd_ = loc[(size_t)idx*4 + i] - g[i];
                float ad = fabsf(dd_);
                ll += (ad < 1.0f) ? (0.5f*dd_*dd_) : (ad - 0.5f);
            }
#pragma unroll
            for (int i = 0; i < 3; i++) {
                float e = pose[(size_t)idx*3 + i] - tpz[mt][i];
                lp += e*e;
            }
        }

        const float* v = sconf + tid*CC;
        float m = v[0];
#pragma unroll
        for (int c = 1; c < CC; c++) m = fmaxf(m, v[c]);
        float s = 0.0f;
#pragma unroll
        for (int c = 0; c < CC; c++) s += fexp(v[c] - m);
        float lse = m + logf(s);
        float ce = lse - v[cf];
        if (cf > 0) { d_ceneg[idx] = 0.0f; cepos = ce; }
        else        { d_ceneg[idx] = ce; }
    }

    double rll = (double)ll, rlp = (double)lp, rce = (double)cepos;
    int rnp = np;
#pragma unroll
    for (int s = 16; s > 0; s >>= 1) {
        rll += __shfl_down_sync(0xffffffffu, rll, s);
        rlp += __shfl_down_sync(0xffffffffu, rlp, s);
        rce += __shfl_down_sync(0xffffffffu, rce, s);
        rnp += __shfl_down_sync(0xffffffffu, rnp, s);
    }
    __shared__ double wll[8], wlp[8], wce[8];
    __shared__ int wnp[8];
    int wid = tid >> 5, lane = tid & 31;
    if (lane == 0) { wll[wid] = rll; wlp[wid] = rlp; wce[wid] = rce; wnp[wid] = rnp; }
    __syncthreads();
    if (wid == 0) {
        rll = (lane < 8) ? wll[lane] : 0.0;
        rlp = (lane < 8) ? wlp[lane] : 0.0;
        rce = (lane < 8) ? wce[lane] : 0.0;
        rnp = (lane < 8) ? wnp[lane] : 0;
#pragma unroll
        for (int s = 4; s > 0; s >>= 1) {
            rll += __shfl_down_sync(0xffu, rll, s);
            rlp += __shfl_down_sync(0xffu, rlp, s);
            rce += __shfl_down_sync(0xffu, rce, s);
            rnp += __shfl_down_sync(0xffu, rnp, s);
        }
        if (lane == 0) {
            int part = b*NCE + blockIdx.x;
            d_pll[part] = rll; d_plp[part] = rlp; d_pce[part] = rce;
            d_npb[part] = rnp;
        }
    }
}

// Exact top-k sum via smem 4-pass byte radix select; per-warp histograms.
__global__ void __launch_bounds__(1024) k_topk() {
    const int b = blockIdx.x, tid = threadIdx.x;
    const int T = 1024;
    const int wid = tid >> 5, lane = tid & 31;
    __shared__ float sce[DD];
    __shared__ int hist[32*256];        // per-warp
    __shared__ int histc[256];          // combined
    __shared__ unsigned s_prefix;
    __shared__ int s_rem;
    __shared__ int s_k;

    if (tid < 32) {
        int s = (tid < NCE) ? d_npb[b*NCE + tid] : 0;
        if (tid + 32 < NCE) s += d_npb[b*NCE + tid + 32];
#pragma unroll
        for (int st = 16; st > 0; st >>= 1) s += __shfl_down_sync(0xffffffffu, s, st);
        if (tid == 0) {
            int k = s * 3; if (k > DD) k = DD;
            s_k = k; s_prefix = 0u; s_rem = k;
        }
    }
    {
        const float4* ce4 = (const float4*)(d_ceneg + (size_t)b * DD);
        float4* s4 = (float4*)sce;
        for (int i = tid; i < DD/4; i += T) s4[i] = ce4[i];
    }
    __syncthreads();
    if (s_k <= 0) { if (tid == 0) d_topksum[b] = 0.0; return; }

#pragma unroll
    for (int pass = 3; pass >= 0; pass--) {
#pragma unroll
        for (int i = 0; i < 8; i++) hist[i*1024 + tid] = 0;
        __syncthreads();
        const unsigned pref = s_prefix;
        const int sh = pass * 8;
        int* myhist = hist + wid*256;
        for (int d = tid; d < DD; d += T) {
            unsigned u = __float_as_uint(sce[d]);
            bool ok = (pass == 3) || ((u >> (sh + 8)) == (pref >> (sh + 8)));
            if (ok) {
                int dig = (u >> sh) & 255;
                unsigned act = __activemask();
                unsigned mm = __match_any_sync(act, dig);
                if (lane == (__ffs(mm) - 1))
                    atomicAdd(&myhist[dig], __popc(mm));
            }
        }
        __syncthreads();
        if (tid < 256) {
            int s = 0;
#pragma unroll
            for (int w = 0; w < 32; w++) s += hist[w*256 + tid];
            histc[tid] = s;
        }
        __syncthreads();
        if (tid < 32) {
            const int base = 255 - tid*8;
            int binv[8]; int s0 = 0;
#pragma unroll
            for (int i = 0; i < 8; i++) { binv[i] = histc[base - i]; s0 += binv[i]; }
            int pre = s0;
#pragma unroll
            for (int off = 1; off < 32; off <<= 1) {
                int o = __shfl_up_sync(0xffffffffu, pre, off);
                if (tid >= off) pre += o;
            }
            int excl = pre - s0;
            int rem = s_rem;
            if ((excl < rem) && (pre >= rem)) {
                int cum = excl; int dg = base; int nrem = rem;
#pragma unroll
                for (int i = 0; i < 8; i++) {
                    if (cum + binv[i] >= rem) { dg = base - i; nrem = rem - cum; break; }
                    cum += binv[i];
                }
                s_prefix = pref | ((unsigned)dg << sh);
                s_rem = nrem;
            }
        }
        __syncthreads();
    }

    const unsigned uT = s_prefix;
    const float Tv = __uint_as_float(uT);
    const int k = s_k;
    double sg = 0.0; int cg = 0;
    for (int d = tid; d < DD; d += T) {
        float v = sce[d];
        if (__float_as_uint(v) > uT) { sg += (double)v; cg++; }
    }
#pragma unroll
    for (int s = 16; s > 0; s >>= 1) {
        sg += __shfl_down_sync(0xffffffffu, sg, s);
        cg += __shfl_down_sync(0xffffffffu, cg, s);
    }
    __shared__ double wsg[32];
    __shared__ int wcg[32];
    if (lane == 0) { wsg[wid] = sg; wcg[wid] = cg; }
    __syncthreads();
    if (tid == 0) {
        double tsg = 0.0; int tcg = 0;
        for (int i = 0; i < 32; i++) { tsg += wsg[i]; tcg += wcg[i]; }
        d_topksum[b] = tsg + (double)(k - tcg) * (double)Tv;
    }
}

// Ordered compaction — all d_ct accesses via smem stage (no serial global chains).
__global__ void k_compact(const float* __restrict__ line,
                          const float* __restrict__ tgt) {
    const int b = blockIdx.x, tid = threadIdx.x;
    const int CHP = (DD + 255) / 256; // 35
    int d0 = tid * CHP;
    int d1 = d0 + CHP; if (d1 > DD) d1 = DD;

    __shared__ unsigned char sct[DD];   // 8732 bytes, DD = 4*2183
    {
        const unsigned* src = (const unsigned*)(d_ct + (size_t)b*DD);
        unsigned* dst = (unsigned*)sct;
        for (int i = tid; i < DD/4; i += 256) dst[i] = src[i];
    }

    __shared__ int snb[BB];
    __shared__ int s_off, s_tot;
    if (tid < BB) {
        int s = 0;
        for (int c = 0; c < NCE; c++) s += d_npb[tid*NCE + c];
        snb[tid] = s;
    }
    __syncthreads();
    if (tid == 0) {
        int acc = 0, off = 0;
        for (int i = 0; i < BB; i++) { if (i == b) off = acc; acc += snb[i]; }
        s_off = off; s_tot = acc;
    }

    int cnt = 0;
    for (int d = d0; d < d1; d++) if ((sct[d] & 31) > 0) cnt++;
    __shared__ int sc[256];
    sc[tid] = cnt;
    __syncthreads();
    if (tid == 0) {
        int acc = 0;
        for (int i = 0; i < 256; i++) { int c = sc[i]; sc[i] = acc; acc += c; }
    }
    __syncthreads();

    int rank = s_off + sc[tid];
    for (int d = d0; d < d1 && rank < KK; d++) {
        unsigned char ct = sct[d];
        int cf = ct & 31;
        if (cf > 0) {
            int idx = b*DD + d;
            int slot = rank++;
            d_lab[slot] = cf;
            d_val[slot] = 1;
#pragma unroll
            for (int l = 0; l < LL; l++) d_emb[slot*LL + l] = line[(size_t)idx*LL + l];
            int t = ct >> 5;
            const float* p = tgt + (size_t)(b*OO + t)*9;
            d_qp[slot*3+0] = p[5]; d_qp[slot*3+1] = p[6]; d_qp[slot*3+2] = p[7];
        }
    }

    if (b == 0) {
        __syncthreads();
        __shared__ int smap[256];
        if (tid == 0) {
            int Pt = s_tot;
            int nr = 0;
            for (int d = 0; d < 256; d++) {
                int slot = -1;
                if ((sct[d] & 31) == 0) {
                    int s2 = Pt + nr; nr++;
                    if (s2 < KK) slot = s2;
                }
                smap[d] = slot;
            }
        }
        __syncthreads();
        int d = tid;
        int slot = smap[d];
        if (slot >= 0) {
            unsigned char ct = sct[d];
            d_lab[slot] = ct & 31;
            d_val[slot] = 0;
#pragma unroll
            for (int l = 0; l < LL; l++) d_emb[slot*LL + l] = line[(size_t)d*LL + l];
            int t = ct >> 5;
            const float* p = tgt + (size_t)t*9;
            d_qp[slot*3+0] = p[5]; d_qp[slot*3+1] = p[6]; d_qp[slot*3+2] = p[7];
        }
    }
}

// Fused pairwise + triplet. Block i (anchor), thread j (partner). Partials per block.
__global__ void k_pairstrip() {
    int i = blockIdx.x, j = threadIdx.x;
    __shared__ float ei[LL], ni[LL], qi[3];
    __shared__ int labi, vali;
    __shared__ float sdist[KK];
    __shared__ unsigned pm[8], nm[8];

    if (j < LL) ei[j] = d_emb[i*LL + j];
    if (j == 0) {
        labi = d_lab[i]; vali = d_val[i];
        qi[0] = d_qp[i*3+0]; qi[1] = d_qp[i*3+1]; qi[2] = d_qp[i*3+2];
    }
    __syncthreads();
    if (j == 0) {
        float s = 0.0f;
        for (int l = 0; l < LL; l++) s += ei[l]*ei[l];
        float n = fmaxf(sqrtf(s), 1e-12f);
        for (int l = 0; l < LL; l++) ni[l] = ei[l] / n;
    }
    __syncthreads();

    float ej[LL];
#pragma unroll
    for (int l = 0; l < LL; l++) ej[l] = d_emb[j*LL + l];
    float s = 0.0f;
#pragma unroll
    for (int l = 0; l < LL; l++) s += ej[l]*ej[l];
    float rnj = 1.0f / fmaxf(sqrtf(s), 1e-12f);

    float sq = 0.0f, esq = 0.0f;
#pragma unroll
    for (int l = 0; l < LL; l++) {
        float dn = ni[l] - ej[l]*rnj; sq  += dn*dn;
        float de = ei[l] - ej[l];     esq += de*de;
    }
    float dist = sqrtf(fmaxf(sq, 1e-12f));
    sdist[j] = dist;

    float qsq = 0.0f;
#pragma unroll
    for (int c = 0; c < 3; c++) { float dq = qi[c] - d_qp[j*3+c]; qsq += dq*dq; }

    bool vp   = vali && d_val[j] && (i != j);
    bool same = (labi == d_lab[j]);
    bool pp = vp &&  same && (dist > 0.2f);
    bool np = vp && !same && (dist < 0.8f);

    unsigned pb = __ballot_sync(0xffffffffu, pp);
    unsigned nb = __ballot_sync(0xffffffffu, np);
    if ((j & 31) == 0) { pm[j>>5] = pb; nm[j>>5] = nb; }

    double dk = pp ? (double)((esq - qsq) * (esq - qsq)) : 0.0;
    int cp = pp ? 1 : 0, cn = np ? 1 : 0;
#pragma unroll
    for (int st = 16; st > 0; st >>= 1) {
        dk += __shfl_down_sync(0xffffffffu, dk, st);
        cp += __shfl_down_sync(0xffffffffu, cp, st);
        cn += __shfl_down_sync(0xffffffffu, cn, st);
    }
    __shared__ double wdk[8];
    __shared__ int wcp[8], wcn[8];
    int wid = j >> 5, lane = j & 31;
    if (lane == 0) { wdk[wid] = dk; wcp[wid] = cp; wcn[wid] = cn; }
    __syncthreads();
    if (j == 0) {
        double t = 0.0; int p = 0, n = 0;
        for (int w = 0; w < 8; w++) { t += wdk[w]; p += wcp[w]; n += wcn[w]; }
        d_pdesk[i] = t; d_pnpp[i] = p; d_pnnp[i] = n;
    }

    __shared__ int pj[KK];
    __shared__ int npj;
    if (j == 0) {
        int n = 0;
        for (int w = 0; w < 8; w++) {
            unsigned m = pm[w];
            while (m) { int bp = __ffs(m) - 1; pj[n++] = w*32 + bp; m &= (m - 1); }
        }
        npj = n;
    }
    __syncthreads();
    int n = npj;
    if (n == 0) {
        if (j == 0) { d_ptrips[i] = 0.0; d_ptc[i] = 0; }
        return;
    }

    bool isneg = (nm[j >> 5] >> (j & 31)) & 1u;
    double ls = 0.0;
    int lc = 0;
    if (isneg) {
        float dk2 = sdist[j];
        for (int a = 0; a < n; a++) {
            float l = sdist[pj[a]] - dk2 + 0.2f;
            if (l > 0.0f) { ls += (double)l; lc++; }
        }
    }
#pragma unroll
    for (int st = 16; st > 0; st >>= 1) {
        ls += __shfl_down_sync(0xffffffffu, ls, st);
        lc += __shfl_down_sync(0xffffffffu, lc, st);
    }
    __shared__ double wls[8];
    __shared__ int wlc[8];
    if (lane == 0) { wls[wid] = ls; wlc[wid] = lc; }
    __syncthreads();
    if (j == 0) {
        double t = 0.0; int c = 0;
        for (int w = 0; w < 8; w++) { t += wls[w]; c += wlc[w]; }
        d_ptrips[i] = t; d_ptc[i] = c;
    }
}

// Reduce all partials, compute final 5 outputs.
__global__ void k_final(float* __restrict__ out) {
    const int tid = threadIdx.x;
    double ll = 0.0, lp = 0.0, ce = 0.0;
    int np = 0;
    for (int i = tid; i < BB*NCE; i += 256) {
        ll += d_pll[i]; lp += d_plp[i]; ce += d_pce[i]; np += d_npb[i];
    }
    double dsk = 0.0, trp = 0.0;
    int npp = 0, nnp = 0, tc = 0;
    for (int i = tid; i < KK; i += 256) {
        dsk += d_pdesk[i]; trp += d_ptrips[i];
        npp += d_pnpp[i]; nnp += d_pnnp[i]; tc += d_ptc[i];
    }
    if (tid < BB) ce += d_topksum[tid];

#pragma unroll
    for (int s = 16; s > 0; s >>= 1) {
        ll += __shfl_down_sync(0xffffffffu, ll, s);
        lp += __shfl_down_sync(0xffffffffu, lp, s);
        ce += __shfl_down_sync(0xffffffffu, ce, s);
        np += __shfl_down_sync(0xffffffffu, np, s);
        dsk += __shfl_down_sync(0xffffffffu, dsk, s);
        trp += __shfl_down_sync(0xffffffffu, trp, s);
        npp += __shfl_down_sync(0xffffffffu, npp, s);
        nnp += __shfl_down_sync(0xffffffffu, nnp, s);
        tc  += __shfl_down_sync(0xffffffffu, tc, s);
    }
    __shared__ double sll[8], slp[8], sce2[8], sdsk[8], strp[8];
    __shared__ int snp[8], snpp[8], snnp[8], stc[8];
    int wid = tid >> 5, lane = tid & 31;
    if (lane == 0) {
        sll[wid] = ll; slp[wid] = lp; sce2[wid] = ce; snp[wid] = np;
        sdsk[wid] = dsk; strp[wid] = trp; snpp[wid] = npp; snnp[wid] = nnp; stc[wid] = tc;
    }
    __syncthreads();
    if (tid == 0) {
        for (int w = 1; w < 8; w++) {
            sll[0] += sll[w]; slp[0] += slp[w]; sce2[0] += sce2[w]; snp[0] += snp[w];
            sdsk[0] += sdsk[w]; strp[0] += strp[w];
            snpp[0] += snpp[w]; snnp[0] += snnp[w]; stc[0] += stc[w];
        }
        double N = (double)snp[0];
        if (N < 1.0) N = 1.0;
        double lossl = sll[0] / N;
        double lossc = sce2[0] / N;
        double lossp = slp[0] / N;

        double dnpp = (snpp[0] < 1) ? 1.0 : (double)snpp[0];
        double losst = strp[0] / (double)((stc[0] < 1) ? 1 : stc[0]);
        long long pn = (long long)snpp[0] + (long long)snnp[0];
        double dpn = (pn < 1) ? 1.0 : (double)pn;

        double ldesk = sdsk[0] / dnpp + losst / dpn;
        ldesk = ldesk / dnpp / 32.0;

        out[0] = (float)lossl;
        out[1] = (float)lossc;
        out[2] = (float)lossp;
        out[3] = (float)ldesk;
        out[4] = (float)losst;
    }
}

// ---------------- host launcher ----------------
extern "C" void kernel_launch(void* const* d_in, const int* in_sizes, int n_in,
                              void* d_out, int out_size) {
    const float *loc = 0, *conf = 0, *line = 0, *pose = 0, *dbox = 0, *tgt = 0;
    for (int i = 0; i < n_in; i++) {
        switch (in_sizes[i]) {
            case BB*DD*4:  loc  = (const float*)d_in[i]; break;
            case BB*DD*CC: conf = (const float*)d_in[i]; break;
            case BB*DD*LL: line = (const float*)d_in[i]; break;
            case BB*DD*3:  pose = (const float*)d_in[i]; break;
            case DD*4:     dbox = (const float*)d_in[i]; break;
            case BB*OO*9:  tgt  = (const float*)d_in[i]; break;
            default: break;
        }
    }
    if (!loc)  loc  = (const float*)d_in[0];
    if (!conf) conf = (const float*)d_in[1];
    if (!line) line = (const float*)d_in[2];
    if (!pose) pose = (const float*)d_in[3];
    if (!dbox) dbox = (const float*)d_in[4];
    if (!tgt)  tgt  = (const float*)d_in[5];

    k_match1<<<dim3(NCH, BB), 256>>>(dbox, tgt);
    k_encce<<<dim3(NCE, BB), 256>>>(loc, pose, dbox, tgt, conf);
    k_topk<<<BB, 1024>>>();
    k_compact<<<BB, 256>>>(line, tgt);
    k_pairstrip<<<KK, 256>>>();
    k_final<<<1, 256>>>((float*)d_out);
}

// round 7
// speedup vs baseline: 1.3421x; 1.3421x over previous
#include <cuda_runtime.h>
#include <cuda_bf16.h>
#include <math.h>

#define BB 32
#define DD 8732
#define OO 8
#define CC 21
#define LL 32
#define KK 256
#define NCH 8
#define CH  1092   // NCH*CH = 8736 >= DD
#define NCE 35     // encce chunks per batch (35*256 >= 8732)

// ---------------- device scratch ----------------
__device__ unsigned char d_ct[BB*DD];      // conf (5 bits) | truth idx (3 bits)
__device__ float  d_ceneg[BB*DD];
__device__ unsigned long long d_bestkey[BB*NCH*OO]; // per (batch, chunk, truth)

// per-block partials (no global atomics anywhere)
__device__ double d_pll[BB*NCE], d_plp[BB*NCE], d_pce[BB*NCE];
__device__ int    d_npb[BB*NCE];
__device__ double d_topksum[BB];
__device__ double d_pdesk[KK], d_ptrips[KK];
__device__ int    d_pnpp[KK], d_pnnp[KK], d_ptc[KK];

__device__ float  d_emb[KK*LL];
__device__ int    d_lab[KK];
__device__ float  d_qp[KK*3];
__device__ int    d_val[KK];

// fast exp on the FMA pipe (inputs are x - max <= 0)
__device__ __forceinline__ float fexp(float x) {
    x = fmaxf(x, -80.0f);
    float y = x * 1.442695040888963f;
    float n = rintf(y);
    float f = y - n;                       // [-0.5, 0.5]
    float p = 1.54035303933816e-4f;
    p = fmaf(p, f, 1.33335581464284e-3f);
    p = fmaf(p, f, 9.61812910762848e-3f);
    p = fmaf(p, f, 5.55041086648216e-2f);
    p = fmaf(p, f, 2.40226506959101e-1f);
    p = fmaf(p, f, 6.93147180559945e-1f);
    p = fmaf(p, f, 1.0f);
    return __int_as_float(__float_as_int(p) + (((int)n) << 23));
}

// ---------------- kernels ----------------

// Per-truth best prior within this chunk; one plain store per (block, truth).
__global__ void k_match1(const float* __restrict__ dbox,
                         const float* __restrict__ tgt) {
    const int b = blockIdx.y;
    const int base = blockIdx.x * CH;
    const int tid = threadIdx.x;

    __shared__ float tx1[OO], ty1[OO], tx2[OO], ty2[OO], ta[OO];
    if (tid < OO) {
        const float* p = tgt + (size_t)(b*OO + tid)*9;
        tx1[tid] = p[0]; ty1[tid] = p[1]; tx2[tid] = p[2]; ty2[tid] = p[3];
        ta[tid]  = (p[2]-p[0])*(p[3]-p[1]);
    }
    __syncthreads();

    unsigned long long bk[OO];
#pragma unroll
    for (int t = 0; t < OO; t++) bk[t] = 0ull;

    int dend = base + CH; if (dend > DD) dend = DD;
    for (int d = base + tid; d < dend; d += 256) {
        float4 db = __ldg((const float4*)(dbox + d*4));
        float px1 = db.x - db.z*0.5f, py1 = db.y - db.w*0.5f;
        float px2 = db.x + db.z*0.5f, py2 = db.y + db.w*0.5f;
        float pa = (px2-px1)*(py2-py1);
#pragma unroll
        for (int t = 0; t < OO; t++) {
            float ix = fmaxf(fminf(tx2[t], px2) - fmaxf(tx1[t], px1), 0.0f);
            float iy = fmaxf(fminf(ty2[t], py2) - fmaxf(ty1[t], py1), 0.0f);
            float inter = ix * iy;
            float iou = inter / (ta[t] + pa - inter);
            unsigned long long key =
                ((unsigned long long)__float_as_uint(iou) << 32) |
                (unsigned long long)(0xFFFFFFFFu - (unsigned)d);
            if (key > bk[t]) bk[t] = key;
        }
    }

    __shared__ unsigned long long wk[8][OO];
    int wid = tid >> 5, lane = tid & 31;
#pragma unroll
    for (int t = 0; t < OO; t++) {
        unsigned long long k = bk[t];
#pragma unroll
        for (int s = 16; s > 0; s >>= 1) {
            unsigned long long o = __shfl_down_sync(0xffffffffu, k, s);
            if (o > k) k = o;
        }
        if (lane == 0) wk[wid][t] = k;
    }
    __syncthreads();
    if (tid < OO) {
        unsigned long long k = 0ull;
#pragma unroll
        for (int w = 0; w < 8; w++) if (wk[w][tid] > k) k = wk[w][tid];
        d_bestkey[(b*NCH + blockIdx.x)*OO + tid] = k;
    }
}

// Fused: recompute per-prior best truth, apply overrides, conf_t, encode,
// loc/pose losses, CE. Per-block partial sums (no atomics).
__global__ void k_encce(const float* __restrict__ loc,
                        const float* __restrict__ pose,
                        const float* __restrict__ dbox,
                        const float* __restrict__ tgt,
                        const float* __restrict__ conf) {
    const int b = blockIdx.y;
    const int tid = threadIdx.x;
    const int d = blockIdx.x * 256 + tid;

    __shared__ float tx1[OO], ty1[OO], tx2[OO], ty2[OO], ta[OO];
    __shared__ float tpz[OO][3];
    __shared__ int   tlab[OO], bestd[OO];
    __shared__ float sconf[256*CC];

    if (tid < OO) {
        const float* p = tgt + (size_t)(b*OO + tid)*9;
        tx1[tid] = p[0]; ty1[tid] = p[1]; tx2[tid] = p[2]; ty2[tid] = p[3];
        ta[tid]  = (p[2]-p[0])*(p[3]-p[1]);
        tlab[tid] = (int)p[4];
        tpz[tid][0] = p[5]; tpz[tid][1] = p[6]; tpz[tid][2] = p[7];
        unsigned long long k = 0ull;
#pragma unroll
        for (int c = 0; c < NCH; c++) {
            unsigned long long o = d_bestkey[(b*NCH + c)*OO + tid];
            if (o > k) k = o;
        }
        bestd[tid] = (int)(0xFFFFFFFFu - (unsigned)(k & 0xFFFFFFFFull));
    }
    {
        int d0 = blockIdx.x * 256;
        int nblk = DD - d0; if (nblk > 256) nblk = 256;
        const float* cbase = conf + ((size_t)b*DD + d0)*CC;
        for (int i = tid; i < nblk*CC; i += 256) sconf[i] = cbase[i];
    }
    __syncthreads();

    float ll = 0.0f, lp = 0.0f, cepos = 0.0f;
    int np = 0;
    if (d < DD) {
        int idx = b*DD + d;
        float4 db = __ldg((const float4*)(dbox + d*4));
        float px1 = db.x - db.z*0.5f, py1 = db.y - db.w*0.5f;
        float px2 = db.x + db.z*0.5f, py2 = db.y + db.w*0.5f;
        float pa = (px2-px1)*(py2-py1);
        float mv = -1.0f; int mt = 0;
#pragma unroll
        for (int t = 0; t < OO; t++) {
            float ix = fmaxf(fminf(tx2[t], px2) - fmaxf(tx1[t], px1), 0.0f);
            float iy = fmaxf(fminf(ty2[t], py2) - fmaxf(ty1[t], py1), 0.0f);
            float inter = ix * iy;
            float iou = inter / (ta[t] + pa - inter);
            if (iou > mv) { mv = iou; mt = t; }   // first occurrence over t
        }
#pragma unroll
        for (int t = 0; t < OO; t++) {            // overrides, last t wins
            if (bestd[t] == d) { mv = 2.0f; mt = t; }
        }
        int cf = (mv < 0.5f) ? 0 : (tlab[mt] + 1);
        d_ct[idx] = (unsigned char)(cf | (mt << 5));

        if (cf > 0) {
            np = 1;
            float g0 = ((tx1[mt] + tx2[mt])*0.5f - db.x) / (0.1f * db.z);
            float g1 = ((ty1[mt] + ty2[mt])*0.5f - db.y) / (0.1f * db.w);
            float g2 = logf((tx2[mt] - tx1[mt]) / db.z) / 0.2f;
            float g3 = logf((ty2[mt] - ty1[mt]) / db.w) / 0.2f;
            float g[4] = {g0, g1, g2, g3};
#pragma unroll
            for (int i = 0; i < 4; i++) {
                float dd_ = loc[(size_t)idx*4 + i] - g[i];
                float ad = fabsf(dd_);
                ll += (ad < 1.0f) ? (0.5f*dd_*dd_) : (ad - 0.5f);
            }
#pragma unroll
            for (int i = 0; i < 3; i++) {
                float e = pose[(size_t)idx*3 + i] - tpz[mt][i];
                lp += e*e;
            }
        }

        const float* v = sconf + tid*CC;
        float m = v[0];
#pragma unroll
        for (int c = 1; c < CC; c++) m = fmaxf(m, v[c]);
        float s = 0.0f;
#pragma unroll
        for (int c = 0; c < CC; c++) s += fexp(v[c] - m);
        float lse = m + logf(s);
        float ce = lse - v[cf];
        if (cf > 0) { d_ceneg[idx] = 0.0f; cepos = ce; }
        else        { d_ceneg[idx] = ce; }
    }

    double rll = (double)ll, rlp = (double)lp, rce = (double)cepos;
    int rnp = np;
#pragma unroll
    for (int s = 16; s > 0; s >>= 1) {
        rll += __shfl_down_sync(0xffffffffu, rll, s);
        rlp += __shfl_down_sync(0xffffffffu, rlp, s);
        rce += __shfl_down_sync(0xffffffffu, rce, s);
        rnp += __shfl_down_sync(0xffffffffu, rnp, s);
    }
    __shared__ double wll[8], wlp[8], wce[8];
    __shared__ int wnp[8];
    int wid = tid >> 5, lane = tid & 31;
    if (lane == 0) { wll[wid] = rll; wlp[wid] = rlp; wce[wid] = rce; wnp[wid] = rnp; }
    __syncthreads();
    if (wid == 0) {
        rll = (lane < 8) ? wll[lane] : 0.0;
        rlp = (lane < 8) ? wlp[lane] : 0.0;
        rce = (lane < 8) ? wce[lane] : 0.0;
        rnp = (lane < 8) ? wnp[lane] : 0;
#pragma unroll
        for (int s = 4; s > 0; s >>= 1) {
            rll += __shfl_down_sync(0xffu, rll, s);
            rlp += __shfl_down_sync(0xffu, rlp, s);
            rce += __shfl_down_sync(0xffu, rce, s);
            rnp += __shfl_down_sync(0xffu, rnp, s);
        }
        if (lane == 0) {
            int part = b*NCE + blockIdx.x;
            d_pll[part] = rll; d_plp[part] = rlp; d_pce[part] = rce;
            d_npb[part] = rnp;
        }
    }
}

// Exact top-k sum via smem 4-pass byte radix select; per-warp histograms.
__global__ void __launch_bounds__(1024) k_topk() {
    const int b = blockIdx.x, tid = threadIdx.x;
    const int T = 1024;
    const int wid = tid >> 5, lane = tid & 31;
    __shared__ float sce[DD];
    __shared__ int hist[32*256];        // per-warp
    __shared__ int histc[256];          // combined
    __shared__ unsigned s_prefix;
    __shared__ int s_rem;
    __shared__ int s_k;

    if (tid < 32) {
        int s = (tid < NCE) ? d_npb[b*NCE + tid] : 0;
        if (tid + 32 < NCE) s += d_npb[b*NCE + tid + 32];
#pragma unroll
        for (int st = 16; st > 0; st >>= 1) s += __shfl_down_sync(0xffffffffu, s, st);
        if (tid == 0) {
            int k = s * 3; if (k > DD) k = DD;
            s_k = k; s_prefix = 0u; s_rem = k;
        }
    }
    {
        const float4* ce4 = (const float4*)(d_ceneg + (size_t)b * DD);
        float4* s4 = (float4*)sce;
        for (int i = tid; i < DD/4; i += T) s4[i] = ce4[i];
    }
    __syncthreads();
    if (s_k <= 0) { if (tid == 0) d_topksum[b] = 0.0; return; }

#pragma unroll
    for (int pass = 3; pass >= 0; pass--) {
#pragma unroll
        for (int i = 0; i < 8; i++) hist[i*1024 + tid] = 0;
        __syncthreads();
        const unsigned pref = s_prefix;
        const int sh = pass * 8;
        int* myhist = hist + wid*256;
        for (int d = tid; d < DD; d += T) {
            unsigned u = __float_as_uint(sce[d]);
            bool ok = (pass == 3) || ((u >> (sh + 8)) == (pref >> (sh + 8)));
            if (ok) {
                int dig = (u >> sh) & 255;
                unsigned act = __activemask();
                unsigned mm = __match_any_sync(act, dig);
                if (lane == (__ffs(mm) - 1))
                    atomicAdd(&myhist[dig], __popc(mm));
            }
        }
        __syncthreads();
        if (tid < 256) {
            int s = 0;
#pragma unroll
            for (int w = 0; w < 32; w++) s += hist[w*256 + tid];
            histc[tid] = s;
        }
        __syncthreads();
        if (tid < 32) {
            const int base = 255 - tid*8;
            int binv[8]; int s0 = 0;
#pragma unroll
            for (int i = 0; i < 8; i++) { binv[i] = histc[base - i]; s0 += binv[i]; }
            int pre = s0;
#pragma unroll
            for (int off = 1; off < 32; off <<= 1) {
                int o = __shfl_up_sync(0xffffffffu, pre, off);
                if (tid >= off) pre += o;
            }
            int excl = pre - s0;
            int rem = s_rem;
            if ((excl < rem) && (pre >= rem)) {
                int cum = excl; int dg = base; int nrem = rem;
#pragma unroll
                for (int i = 0; i < 8; i++) {
                    if (cum + binv[i] >= rem) { dg = base - i; nrem = rem - cum; break; }
                    cum += binv[i];
                }
                s_prefix = pref | ((unsigned)dg << sh);
                s_rem = nrem;
            }
        }
        __syncthreads();
    }

    const unsigned uT = s_prefix;
    const float Tv = __uint_as_float(uT);
    const int k = s_k;
    double sg = 0.0; int cg = 0;
    for (int d = tid; d < DD; d += T) {
        float v = sce[d];
        if (__float_as_uint(v) > uT) { sg += (double)v; cg++; }
    }
#pragma unroll
    for (int s = 16; s > 0; s >>= 1) {
        sg += __shfl_down_sync(0xffffffffu, sg, s);
        cg += __shfl_down_sync(0xffffffffu, cg, s);
    }
    __shared__ double wsg[32];
    __shared__ int wcg[32];
    if (lane == 0) { wsg[wid] = sg; wcg[wid] = cg; }
    __syncthreads();
    if (tid == 0) {
        double tsg = 0.0; int tcg = 0;
        for (int i = 0; i < 32; i++) { tsg += wsg[i]; tcg += wcg[i]; }
        d_topksum[b] = tsg + (double)(k - tcg) * (double)Tv;
    }
}

// Fully parallel ordered compaction. Grid (NCE, BB): block (c, b) handles
// priors [c*256, c*256+256) of batch b. Slot offsets from d_npb prefix;
// ballot scans; cooperative coalesced row copies. Block (0,0) also places
// the negatives (slots P_total..255, provably among batch-0 priors 0..255).
__global__ void k_compact(const float* __restrict__ line,
                          const float* __restrict__ tgt) {
    const int b = blockIdx.y, c = blockIdx.x;
    const int tid = threadIdx.x;
    const int d = c*256 + tid;
    const int flatChunk = b*NCE + c;
    const int wid = tid >> 5, lane = tid & 31;

    // slot offset for this chunk + total positives
    __shared__ int s_off, s_tot;
    {
        int lo = 0, to = 0;
        for (int i = tid; i < BB*NCE; i += 256) {
            int v = d_npb[i];
            to += v;
            if (i < flatChunk) lo += v;
        }
#pragma unroll
        for (int s = 16; s > 0; s >>= 1) {
            lo += __shfl_down_sync(0xffffffffu, lo, s);
            to += __shfl_down_sync(0xffffffffu, to, s);
        }
        __shared__ int wlo[8], wto[8];
        if (lane == 0) { wlo[wid] = lo; wto[wid] = to; }
        __syncthreads();
        if (tid == 0) {
            int a = 0, t2 = 0;
#pragma unroll
            for (int w = 0; w < 8; w++) { a += wlo[w]; t2 += wto[w]; }
            s_off = a; s_tot = t2;
        }
        __syncthreads();
    }
    if (s_off >= KK && !(b == 0 && c == 0)) return;  // nothing to place here

    unsigned char ct = 0;
    bool pos = false;
    if (d < DD) { ct = d_ct[(size_t)b*DD + d]; pos = (ct & 31) > 0; }

    // block exclusive scan of pos
    unsigned bal = __ballot_sync(0xffffffffu, pos);
    int wpre = __popc(bal & ((1u << lane) - 1u));
    __shared__ int wcnt[8], woff[8];
    if (lane == 0) wcnt[wid] = __popc(bal);
    __syncthreads();
    if (tid == 0) {
        int a = 0;
#pragma unroll
        for (int w = 0; w < 8; w++) { woff[w] = a; a += wcnt[w]; }
    }
    __syncthreads();
    int totpos = woff[7] + wcnt[7];
    int rank = s_off + woff[wid] + wpre;

    __shared__ int pd[256], pslot[256];
    __shared__ unsigned char pct[256];
    if (pos && rank < KK) {
        int li = woff[wid] + wpre;
        pd[li] = d; pslot[li] = rank; pct[li] = ct;
    }
    __syncthreads();
    int m = totpos;
    {
        int cap = KK - s_off; if (cap < 0) cap = 0;
        if (m > cap) m = cap;
    }

    // cooperative coalesced copy of m rows
    for (int i = tid; i < m*LL; i += 256) {
        int p = i >> 5, l = i & 31;
        d_emb[pslot[p]*LL + l] = line[((size_t)b*DD + pd[p])*(size_t)LL + l];
    }
    if (tid < m) {
        int slot = pslot[tid];
        unsigned char cc = pct[tid];
        d_lab[slot] = cc & 31;
        d_val[slot] = 1;
        int t = cc >> 5;
        const float* p = tgt + (size_t)(b*OO + t)*9;
        d_qp[slot*3+0] = p[5]; d_qp[slot*3+1] = p[6]; d_qp[slot*3+2] = p[7];
    }

    // negatives: block (0,0) only; they fill slots [s_tot, 256) from priors 0..255
    if (b == 0 && c == 0 && s_tot < KK) {
        __syncthreads();
        bool neg = !pos;                      // d == tid < 256 <= DD here
        unsigned bal2 = __ballot_sync(0xffffffffu, neg);
        int wpre2 = __popc(bal2 & ((1u << lane) - 1u));
        __shared__ int wcnt2[8], woff2[8];
        if (lane == 0) wcnt2[wid] = __popc(bal2);
        __syncthreads();
        if (tid == 0) {
            int a = 0;
#pragma unroll
            for (int w = 0; w < 8; w++) { woff2[w] = a; a += wcnt2[w]; }
        }
        __syncthreads();
        int totneg = woff2[7] + wcnt2[7];
        int nrank = s_tot + woff2[wid] + wpre2;
        __shared__ int nd[256], nslot[256];
        __shared__ unsigned char nct[256];
        if (neg && nrank < KK) {
            int li = woff2[wid] + wpre2;
            nd[li] = d; nslot[li] = nrank; nct[li] = ct;
        }
        __syncthreads();
        int mn = totneg;
        {
            int cap = KK - s_tot; if (cap < 0) cap = 0;
            if (mn > cap) mn = cap;
        }
        for (int i = tid; i < mn*LL; i += 256) {
            int p = i >> 5, l = i & 31;
            d_emb[nslot[p]*LL + l] = line[(size_t)nd[p]*(size_t)LL + l];
        }
        if (tid < mn) {
            int slot = nslot[tid];
            unsigned char cc = nct[tid];
            d_lab[slot] = cc & 31;
            d_val[slot] = 0;
            int t = cc >> 5;
            const float* p = tgt + (size_t)t*9;
            d_qp[slot*3+0] = p[5]; d_qp[slot*3+1] = p[6]; d_qp[slot*3+2] = p[7];
        }
    }
}

// Fused pairwise + triplet. Block i (anchor), thread j (partner). Partials per block.
__global__ void k_pairstrip() {
    int i = blockIdx.x, j = threadIdx.x;
    __shared__ float ei[LL], ni[LL], qi[3];
    __shared__ int labi, vali;
    __shared__ float sdist[KK];
    __shared__ unsigned pm[8], nm[8];

    if (j < LL) ei[j] = d_emb[i*LL + j];
    if (j == 0) {
        labi = d_lab[i]; vali = d_val[i];
        qi[0] = d_qp[i*3+0]; qi[1] = d_qp[i*3+1]; qi[2] = d_qp[i*3+2];
    }
    __syncthreads();
    if (j == 0) {
        float s = 0.0f;
        for (int l = 0; l < LL; l++) s += ei[l]*ei[l];
        float n = fmaxf(sqrtf(s), 1e-12f);
        for (int l = 0; l < LL; l++) ni[l] = ei[l] / n;
    }
    __syncthreads();

    float ej[LL];
#pragma unroll
    for (int l = 0; l < LL; l++) ej[l] = d_emb[j*LL + l];
    float s = 0.0f;
#pragma unroll
    for (int l = 0; l < LL; l++) s += ej[l]*ej[l];
    float rnj = 1.0f / fmaxf(sqrtf(s), 1e-12f);

    float sq = 0.0f, esq = 0.0f;
#pragma unroll
    for (int l = 0; l < LL; l++) {
        float dn = ni[l] - ej[l]*rnj; sq  += dn*dn;
        float de = ei[l] - ej[l];     esq += de*de;
    }
    float dist = sqrtf(fmaxf(sq, 1e-12f));
    sdist[j] = dist;

    float qsq = 0.0f;
#pragma unroll
    for (int c = 0; c < 3; c++) { float dq = qi[c] - d_qp[j*3+c]; qsq += dq*dq; }

    bool vp   = vali && d_val[j] && (i != j);
    bool same = (labi == d_lab[j]);
    bool pp = vp &&  same && (dist > 0.2f);
    bool np = vp && !same && (dist < 0.8f);

    unsigned pb = __ballot_sync(0xffffffffu, pp);
    unsigned nb = __ballot_sync(0xffffffffu, np);
    if ((j & 31) == 0) { pm[j>>5] = pb; nm[j>>5] = nb; }

    double dk = pp ? (double)((esq - qsq) * (esq - qsq)) : 0.0;
    int cp = pp ? 1 : 0, cn = np ? 1 : 0;
#pragma unroll
    for (int st = 16; st > 0; st >>= 1) {
        dk += __shfl_down_sync(0xffffffffu, dk, st);
        cp += __shfl_down_sync(0xffffffffu, cp, st);
        cn += __shfl_down_sync(0xffffffffu, cn, st);
    }
    __shared__ double wdk[8];
    __shared__ int wcp[8], wcn[8];
    int wid = j >> 5, lane = j & 31;
    if (lane == 0) { wdk[wid] = dk; wcp[wid] = cp; wcn[wid] = cn; }
    __syncthreads();
    if (j == 0) {
        double t = 0.0; int p = 0, n = 0;
        for (int w = 0; w < 8; w++) { t += wdk[w]; p += wcp[w]; n += wcn[w]; }
        d_pdesk[i] = t; d_pnpp[i] = p; d_pnnp[i] = n;
    }

    __shared__ int pj[KK];
    __shared__ int npj;
    if (j == 0) {
        int n = 0;
        for (int w = 0; w < 8; w++) {
            unsigned m = pm[w];
            while (m) { int bp = __ffs(m) - 1; pj[n++] = w*32 + bp; m &= (m - 1); }
        }
        npj = n;
    }
    __syncthreads();
    int n = npj;
    if (n == 0) {
        if (j == 0) { d_ptrips[i] = 0.0; d_ptc[i] = 0; }
        return;
    }

    bool isneg = (nm[j >> 5] >> (j & 31)) & 1u;
    double ls = 0.0;
    int lc = 0;
    if (isneg) {
        float dk2 = sdist[j];
        for (int a = 0; a < n; a++) {
            float l = sdist[pj[a]] - dk2 + 0.2f;
            if (l > 0.0f) { ls += (double)l; lc++; }
        }
    }
#pragma unroll
    for (int st = 16; st > 0; st >>= 1) {
        ls += __shfl_down_sync(0xffffffffu, ls, st);
        lc += __shfl_down_sync(0xffffffffu, lc, st);
    }
    __shared__ double wls[8];
    __shared__ int wlc[8];
    if (lane == 0) { wls[wid] = ls; wlc[wid] = lc; }
    __syncthreads();
    if (j == 0) {
        double t = 0.0; int c = 0;
        for (int w = 0; w < 8; w++) { t += wls[w]; c += wlc[w]; }
        d_ptrips[i] = t; d_ptc[i] = c;
    }
}

// Reduce all partials, compute final 5 outputs.
__global__ void k_final(float* __restrict__ out) {
    const int tid = threadIdx.x;
    double ll = 0.0, lp = 0.0, ce = 0.0;
    int np = 0;
    for (int i = tid; i < BB*NCE; i += 256) {
        ll += d_pll[i]; lp += d_plp[i]; ce += d_pce[i]; np += d_npb[i];
    }
    double dsk = 0.0, trp = 0.0;
    int npp = 0, nnp = 0, tc = 0;
    for (int i = tid; i < KK; i += 256) {
        dsk += d_pdesk[i]; trp += d_ptrips[i];
        npp += d_pnpp[i]; nnp += d_pnnp[i]; tc += d_ptc[i];
    }
    if (tid < BB) ce += d_topksum[tid];

#pragma unroll
    for (int s = 16; s > 0; s >>= 1) {
        ll += __shfl_down_sync(0xffffffffu, ll, s);
        lp += __shfl_down_sync(0xffffffffu, lp, s);
        ce += __shfl_down_sync(0xffffffffu, ce, s);
        np += __shfl_down_sync(0xffffffffu, np, s);
        dsk += __shfl_down_sync(0xffffffffu, dsk, s);
        trp += __shfl_down_sync(0xffffffffu, trp, s);
        npp += __shfl_down_sync(0xffffffffu, npp, s);
        nnp += __shfl_down_sync(0xffffffffu, nnp, s);
        tc  += __shfl_down_sync(0xffffffffu, tc, s);
    }
    __shared__ double sll[8], slp[8], sce2[8], sdsk[8], strp[8];
    __shared__ int snp[8], snpp[8], snnp[8], stc[8];
    int wid = tid >> 5, lane = tid & 31;
    if (lane == 0) {
        sll[wid] = ll; slp[wid] = lp; sce2[wid] = ce; snp[wid] = np;
        sdsk[wid] = dsk; strp[wid] = trp; snpp[wid] = npp; snnp[wid] = nnp; stc[wid] = tc;
    }
    __syncthreads();
    if (tid == 0) {
        for (int w = 1; w < 8; w++) {
            sll[0] += sll[w]; slp[0] += slp[w]; sce2[0] += sce2[w]; snp[0] += snp[w];
            sdsk[0] += sdsk[w]; strp[0] += strp[w];
            snpp[0] += snpp[w]; snnp[0] += snnp[w]; stc[0] += stc[w];
        }
        double N = (double)snp[0];
        if (N < 1.0) N = 1.0;
        double lossl = sll[0] / N;
        double lossc = sce2[0] / N;
        double lossp = slp[0] / N;

        double dnpp = (snpp[0] < 1) ? 1.0 : (double)snpp[0];
        double losst = strp[0] / (double)((stc[0] < 1) ? 1 : stc[0]);
        long long pn = (long long)snpp[0] + (long long)snnp[0];
        double dpn = (pn < 1) ? 1.0 : (double)pn;

        double ldesk = sdsk[0] / dnpp + losst / dpn;
        ldesk = ldesk / dnpp / 32.0;

        out[0] = (float)lossl;
        out[1] = (float)lossc;
        out[2] = (float)lossp;
        out[3] = (float)ldesk;
        out[4] = (float)losst;
    }
}

// ---------------- host launcher ----------------
extern "C" void kernel_launch(void* const* d_in, const int* in_sizes, int n_in,
                              void* d_out, int out_size) {
    const float *loc = 0, *conf = 0, *line = 0, *pose = 0, *dbox = 0, *tgt = 0;
    for (int i = 0; i < n_in; i++) {
        switch (in_sizes[i]) {
            case BB*DD*4:  loc  = (const float*)d_in[i]; break;
            case BB*DD*CC: conf = (const float*)d_in[i]; break;
            case BB*DD*LL: line = (const float*)d_in[i]; break;
            case BB*DD*3:  pose = (const float*)d_in[i]; break;
            case DD*4:     dbox = (const float*)d_in[i]; break;
            case BB*OO*9:  tgt  = (const float*)d_in[i]; break;
            default: break;
        }
    }
    if (!loc)  loc  = (const float*)d_in[0];
    if (!conf) conf = (const float*)d_in[1];
    if (!line) line = (const float*)d_in[2];
    if (!pose) pose = (const float*)d_in[3];
    if (!dbox) dbox = (const float*)d_in[4];
    if (!tgt)  tgt  = (const float*)d_in[5];

    k_match1<<<dim3(NCH, BB), 256>>>(dbox, tgt);
    k_encce<<<dim3(NCE, BB), 256>>>(loc, pose, dbox, tgt, conf);
    k_topk<<<BB, 1024>>>();
    k_compact<<<dim3(NCE, BB), 256>>>(line, tgt);
    k_pairstrip<<<KK, 256>>>();
    k_final<<<1, 256>>>((float*)d_out);
}

// round 8
// speedup vs baseline: 1.5703x; 1.1701x over previous
#include <cuda_runtime.h>
#include <cuda_bf16.h>
#include <math.h>

#define BB 32
#define DD 8732
#define OO 8
#define CC 21
#define LL 32
#define KK 256
#define NCH 8
#define CH  1092   // NCH*CH = 8736 >= DD
#define NCE 35     // encce chunks per batch (35*256 >= 8732)

// ---------------- device scratch ----------------
__device__ unsigned char d_ct[BB*DD];      // conf (5 bits) | truth idx (3 bits)
__device__ float  d_ceneg[BB*DD];
__device__ unsigned long long d_bestkey[BB*NCH*OO]; // per (batch, chunk, truth)

// per-block partials (no global atomics anywhere)
__device__ double d_pll[BB*NCE], d_plp[BB*NCE], d_pce[BB*NCE];
__device__ int    d_npb[BB*NCE];
__device__ double d_topksum[BB];
__device__ double d_pdesk[KK], d_ptrips[KK];
__device__ int    d_pnpp[KK], d_pnnp[KK], d_ptc[KK];

__device__ float  d_emb[KK*LL];
__device__ int    d_lab[KK];
__device__ float  d_qp[KK*3];
__device__ int    d_val[KK];

// fast exp on the FMA pipe (inputs are x - max <= 0)
__device__ __forceinline__ float fexp(float x) {
    x = fmaxf(x, -80.0f);
    float y = x * 1.442695040888963f;
    float n = rintf(y);
    float f = y - n;                       // [-0.5, 0.5]
    float p = 1.54035303933816e-4f;
    p = fmaf(p, f, 1.33335581464284e-3f);
    p = fmaf(p, f, 9.61812910762848e-3f);
    p = fmaf(p, f, 5.55041086648216e-2f);
    p = fmaf(p, f, 2.40226506959101e-1f);
    p = fmaf(p, f, 6.93147180559945e-1f);
    p = fmaf(p, f, 1.0f);
    return __int_as_float(__float_as_int(p) + (((int)n) << 23));
}

// ---------------- kernels ----------------

// Per-truth best prior within this chunk; one plain store per (block, truth).
__global__ void k_match1(const float* __restrict__ dbox,
                         const float* __restrict__ tgt) {
    const int b = blockIdx.y;
    const int base = blockIdx.x * CH;
    const int tid = threadIdx.x;

    __shared__ float tx1[OO], ty1[OO], tx2[OO], ty2[OO], ta[OO];
    if (tid < OO) {
        const float* p = tgt + (size_t)(b*OO + tid)*9;
        tx1[tid] = p[0]; ty1[tid] = p[1]; tx2[tid] = p[2]; ty2[tid] = p[3];
        ta[tid]  = (p[2]-p[0])*(p[3]-p[1]);
    }
    __syncthreads();

    unsigned long long bk[OO];
#pragma unroll
    for (int t = 0; t < OO; t++) bk[t] = 0ull;

    int dend = base + CH; if (dend > DD) dend = DD;
    for (int d = base + tid; d < dend; d += 256) {
        float4 db = __ldg((const float4*)(dbox + d*4));
        float px1 = db.x - db.z*0.5f, py1 = db.y - db.w*0.5f;
        float px2 = db.x + db.z*0.5f, py2 = db.y + db.w*0.5f;
        float pa = (px2-px1)*(py2-py1);
#pragma unroll
        for (int t = 0; t < OO; t++) {
            float ix = fmaxf(fminf(tx2[t], px2) - fmaxf(tx1[t], px1), 0.0f);
            float iy = fmaxf(fminf(ty2[t], py2) - fmaxf(ty1[t], py1), 0.0f);
            float inter = ix * iy;
            float iou = inter / (ta[t] + pa - inter);
            unsigned long long key =
                ((unsigned long long)__float_as_uint(iou) << 32) |
                (unsigned long long)(0xFFFFFFFFu - (unsigned)d);
            if (key > bk[t]) bk[t] = key;
        }
    }

    __shared__ unsigned long long wk[8][OO];
    int wid = tid >> 5, lane = tid & 31;
#pragma unroll
    for (int t = 0; t < OO; t++) {
        unsigned long long k = bk[t];
#pragma unroll
        for (int s = 16; s > 0; s >>= 1) {
            unsigned long long o = __shfl_down_sync(0xffffffffu, k, s);
            if (o > k) k = o;
        }
        if (lane == 0) wk[wid][t] = k;
    }
    __syncthreads();
    if (tid < OO) {
        unsigned long long k = 0ull;
#pragma unroll
        for (int w = 0; w < 8; w++) if (wk[w][tid] > k) k = wk[w][tid];
        d_bestkey[(b*NCH + blockIdx.x)*OO + tid] = k;
    }
}

// Fused: recompute per-prior best truth, apply overrides, conf_t, encode,
// loc/pose losses, CE. Per-block partial sums (no atomics).
__global__ void k_encce(const float* __restrict__ loc,
                        const float* __restrict__ pose,
                        const float* __restrict__ dbox,
                        const float* __restrict__ tgt,
                        const float* __restrict__ conf) {
    const int b = blockIdx.y;
    const int tid = threadIdx.x;
    const int d = blockIdx.x * 256 + tid;

    __shared__ float tx1[OO], ty1[OO], tx2[OO], ty2[OO], ta[OO];
    __shared__ float tpz[OO][3];
    __shared__ int   tlab[OO], bestd[OO];
    __shared__ float sconf[256*CC];

    if (tid < OO) {
        const float* p = tgt + (size_t)(b*OO + tid)*9;
        tx1[tid] = p[0]; ty1[tid] = p[1]; tx2[tid] = p[2]; ty2[tid] = p[3];
        ta[tid]  = (p[2]-p[0])*(p[3]-p[1]);
        tlab[tid] = (int)p[4];
        tpz[tid][0] = p[5]; tpz[tid][1] = p[6]; tpz[tid][2] = p[7];
        unsigned long long k = 0ull;
#pragma unroll
        for (int c = 0; c < NCH; c++) {
            unsigned long long o = d_bestkey[(b*NCH + c)*OO + tid];
            if (o > k) k = o;
        }
        bestd[tid] = (int)(0xFFFFFFFFu - (unsigned)(k & 0xFFFFFFFFull));
    }
    // coalesced float4 stage of this block's conf tile (always 16B-aligned:
    // offsets are multiples of 5376 floats; tile float count divisible by 4)
    {
        int d0 = blockIdx.x * 256;
        int nblk = DD - d0; if (nblk > 256) nblk = 256;
        int nflt = nblk * CC;
        const float4* c4 = (const float4*)(conf + ((size_t)b*DD + d0)*CC);
        float4* s4 = (float4*)sconf;
        for (int i = tid; i < (nflt >> 2); i += 256) s4[i] = c4[i];
    }
    __syncthreads();

    float ll = 0.0f, lp = 0.0f, cepos = 0.0f;
    int np = 0;
    if (d < DD) {
        int idx = b*DD + d;
        float4 db = __ldg((const float4*)(dbox + d*4));
        float px1 = db.x - db.z*0.5f, py1 = db.y - db.w*0.5f;
        float px2 = db.x + db.z*0.5f, py2 = db.y + db.w*0.5f;
        float pa = (px2-px1)*(py2-py1);
        float mv = -1.0f; int mt = 0;
#pragma unroll
        for (int t = 0; t < OO; t++) {
            float ix = fmaxf(fminf(tx2[t], px2) - fmaxf(tx1[t], px1), 0.0f);
            float iy = fmaxf(fminf(ty2[t], py2) - fmaxf(ty1[t], py1), 0.0f);
            float inter = ix * iy;
            float iou = inter / (ta[t] + pa - inter);
            if (iou > mv) { mv = iou; mt = t; }   // first occurrence over t
        }
#pragma unroll
        for (int t = 0; t < OO; t++) {            // overrides, last t wins
            if (bestd[t] == d) { mv = 2.0f; mt = t; }
        }
        int cf = (mv < 0.5f) ? 0 : (tlab[mt] + 1);
        d_ct[idx] = (unsigned char)(cf | (mt << 5));

        if (cf > 0) {
            np = 1;
            float g0 = ((tx1[mt] + tx2[mt])*0.5f - db.x) / (0.1f * db.z);
            float g1 = ((ty1[mt] + ty2[mt])*0.5f - db.y) / (0.1f * db.w);
            float g2 = logf((tx2[mt] - tx1[mt]) / db.z) / 0.2f;
            float g3 = logf((ty2[mt] - ty1[mt]) / db.w) / 0.2f;
            float g[4] = {g0, g1, g2, g3};
#pragma unroll
            for (int i = 0; i < 4; i++) {
                float dd_ = loc[(size_t)idx*4 + i] - g[i];
                float ad = fabsf(dd_);
                ll += (ad < 1.0f) ? (0.5f*dd_*dd_) : (ad - 0.5f);
            }
#pragma unroll
            for (int i = 0; i < 3; i++) {
                float e = pose[(size_t)idx*3 + i] - tpz[mt][i];
                lp += e*e;
            }
        }

        const float* v = sconf + tid*CC;
        float m = v[0];
#pragma unroll
        for (int c = 1; c < CC; c++) m = fmaxf(m, v[c]);
        float s = 0.0f;
#pragma unroll
        for (int c = 0; c < CC; c++) s += fexp(v[c] - m);
        float lse = m + logf(s);
        float ce = lse - v[cf];
        if (cf > 0) { d_ceneg[idx] = 0.0f; cepos = ce; }
        else        { d_ceneg[idx] = ce; }
    }

    double rll = (double)ll, rlp = (double)lp, rce = (double)cepos;
    int rnp = np;
#pragma unroll
    for (int s = 16; s > 0; s >>= 1) {
        rll += __shfl_down_sync(0xffffffffu, rll, s);
        rlp += __shfl_down_sync(0xffffffffu, rlp, s);
        rce += __shfl_down_sync(0xffffffffu, rce, s);
        rnp += __shfl_down_sync(0xffffffffu, rnp, s);
    }
    __shared__ double wll[8], wlp[8], wce[8];
    __shared__ int wnp[8];
    int wid = tid >> 5, lane = tid & 31;
    if (lane == 0) { wll[wid] = rll; wlp[wid] = rlp; wce[wid] = rce; wnp[wid] = rnp; }
    __syncthreads();
    if (wid == 0) {
        rll = (lane < 8) ? wll[lane] : 0.0;
        rlp = (lane < 8) ? wlp[lane] : 0.0;
        rce = (lane < 8) ? wce[lane] : 0.0;
        rnp = (lane < 8) ? wnp[lane] : 0;
#pragma unroll
        for (int s = 4; s > 0; s >>= 1) {
            rll += __shfl_down_sync(0xffu, rll, s);
            rlp += __shfl_down_sync(0xffu, rlp, s);
            rce += __shfl_down_sync(0xffu, rce, s);
            rnp += __shfl_down_sync(0xffu, rnp, s);
        }
        if (lane == 0) {
            int part = b*NCE + blockIdx.x;
            d_pll[part] = rll; d_plp[part] = rlp; d_pce[part] = rce;
            d_npb[part] = rnp;
        }
    }
}

// Exact top-k sum via smem 4-pass byte radix select; per-warp histograms.
__global__ void __launch_bounds__(1024) k_topk() {
    const int b = blockIdx.x, tid = threadIdx.x;
    const int T = 1024;
    const int wid = tid >> 5, lane = tid & 31;
    __shared__ float sce[DD];
    __shared__ int hist[32*256];        // per-warp
    __shared__ int histc[256];          // combined
    __shared__ unsigned s_prefix;
    __shared__ int s_rem;
    __shared__ int s_k;

    if (tid < 32) {
        int s = (tid < NCE) ? d_npb[b*NCE + tid] : 0;
        if (tid + 32 < NCE) s += d_npb[b*NCE + tid + 32];
#pragma unroll
        for (int st = 16; st > 0; st >>= 1) s += __shfl_down_sync(0xffffffffu, s, st);
        if (tid == 0) {
            int k = s * 3; if (k > DD) k = DD;
            s_k = k; s_prefix = 0u; s_rem = k;
        }
    }
    {
        const float4* ce4 = (const float4*)(d_ceneg + (size_t)b * DD);
        float4* s4 = (float4*)sce;
        for (int i = tid; i < DD/4; i += T) s4[i] = ce4[i];
    }
    __syncthreads();
    if (s_k <= 0) { if (tid == 0) d_topksum[b] = 0.0; return; }

#pragma unroll
    for (int pass = 3; pass >= 0; pass--) {
#pragma unroll
        for (int i = 0; i < 8; i++) hist[i*1024 + tid] = 0;
        __syncthreads();
        const unsigned pref = s_prefix;
        const int sh = pass * 8;
        int* myhist = hist + wid*256;
        for (int d = tid; d < DD; d += T) {
            unsigned u = __float_as_uint(sce[d]);
            bool ok = (pass == 3) || ((u >> (sh + 8)) == (pref >> (sh + 8)));
            if (ok) {
                int dig = (u >> sh) & 255;
                unsigned act = __activemask();
                unsigned mm = __match_any_sync(act, dig);
                if (lane == (__ffs(mm) - 1))
                    atomicAdd(&myhist[dig], __popc(mm));
            }
        }
        __syncthreads();
        if (tid < 256) {
            int s = 0;
#pragma unroll
            for (int w = 0; w < 32; w++) s += hist[w*256 + tid];
            histc[tid] = s;
        }
        __syncthreads();
        if (tid < 32) {
            const int base = 255 - tid*8;
            int binv[8]; int s0 = 0;
#pragma unroll
            for (int i = 0; i < 8; i++) { binv[i] = histc[base - i]; s0 += binv[i]; }
            int pre = s0;
#pragma unroll
            for (int off = 1; off < 32; off <<= 1) {
                int o = __shfl_up_sync(0xffffffffu, pre, off);
                if (tid >= off) pre += o;
            }
            int excl = pre - s0;
            int rem = s_rem;
            if ((excl < rem) && (pre >= rem)) {
                int cum = excl; int dg = base; int nrem = rem;
#pragma unroll
                for (int i = 0; i < 8; i++) {
                    if (cum + binv[i] >= rem) { dg = base - i; nrem = rem - cum; break; }
                    cum += binv[i];
                }
                s_prefix = pref | ((unsigned)dg << sh);
                s_rem = nrem;
            }
        }
        __syncthreads();
    }

    const unsigned uT = s_prefix;
    const float Tv = __uint_as_float(uT);
    const int k = s_k;
    double sg = 0.0; int cg = 0;
    for (int d = tid; d < DD; d += T) {
        float v = sce[d];
        if (__float_as_uint(v) > uT) { sg += (double)v; cg++; }
    }
#pragma unroll
    for (int s = 16; s > 0; s >>= 1) {
        sg += __shfl_down_sync(0xffffffffu, sg, s);
        cg += __shfl_down_sync(0xffffffffu, cg, s);
    }
    __shared__ double wsg[32];
    __shared__ int wcg[32];
    if (lane == 0) { wsg[wid] = sg; wcg[wid] = cg; }
    __syncthreads();
    if (tid == 0) {
        double tsg = 0.0; int tcg = 0;
        for (int i = 0; i < 32; i++) { tsg += wsg[i]; tcg += wcg[i]; }
        d_topksum[b] = tsg + (double)(k - tcg) * (double)Tv;
    }
}

// Fully parallel ordered compaction. Grid (NCE, BB).
__global__ void k_compact(const float* __restrict__ line,
                          const float* __restrict__ tgt) {
    const int b = blockIdx.y, c = blockIdx.x;
    const int tid = threadIdx.x;
    const int d = c*256 + tid;
    const int flatChunk = b*NCE + c;
    const int wid = tid >> 5, lane = tid & 31;

    __shared__ int s_off, s_tot;
    {
        int lo = 0, to = 0;
        for (int i = tid; i < BB*NCE; i += 256) {
            int v = d_npb[i];
            to += v;
            if (i < flatChunk) lo += v;
        }
#pragma unroll
        for (int s = 16; s > 0; s >>= 1) {
            lo += __shfl_down_sync(0xffffffffu, lo, s);
            to += __shfl_down_sync(0xffffffffu, to, s);
        }
        __shared__ int wlo[8], wto[8];
        if (lane == 0) { wlo[wid] = lo; wto[wid] = to; }
        __syncthreads();
        if (tid == 0) {
            int a = 0, t2 = 0;
#pragma unroll
            for (int w = 0; w < 8; w++) { a += wlo[w]; t2 += wto[w]; }
            s_off = a; s_tot = t2;
        }
        __syncthreads();
    }
    if (s_off >= KK && !(b == 0 && c == 0)) return;

    unsigned char ct = 0;
    bool pos = false;
    if (d < DD) { ct = d_ct[(size_t)b*DD + d]; pos = (ct & 31) > 0; }

    unsigned bal = __ballot_sync(0xffffffffu, pos);
    int wpre = __popc(bal & ((1u << lane) - 1u));
    __shared__ int wcnt[8], woff[8];
    if (lane == 0) wcnt[wid] = __popc(bal);
    __syncthreads();
    if (tid == 0) {
        int a = 0;
#pragma unroll
        for (int w = 0; w < 8; w++) { woff[w] = a; a += wcnt[w]; }
    }
    __syncthreads();
    int totpos = woff[7] + wcnt[7];
    int rank = s_off + woff[wid] + wpre;

    __shared__ int pd[256], pslot[256];
    __shared__ unsigned char pct[256];
    if (pos && rank < KK) {
        int li = woff[wid] + wpre;
        pd[li] = d; pslot[li] = rank; pct[li] = ct;
    }
    __syncthreads();
    int m = totpos;
    {
        int cap = KK - s_off; if (cap < 0) cap = 0;
        if (m > cap) m = cap;
    }

    for (int i = tid; i < m*LL; i += 256) {
        int p = i >> 5, l = i & 31;
        d_emb[pslot[p]*LL + l] = line[((size_t)b*DD + pd[p])*(size_t)LL + l];
    }
    if (tid < m) {
        int slot = pslot[tid];
        unsigned char cc = pct[tid];
        d_lab[slot] = cc & 31;
        d_val[slot] = 1;
        int t = cc >> 5;
        const float* p = tgt + (size_t)(b*OO + t)*9;
        d_qp[slot*3+0] = p[5]; d_qp[slot*3+1] = p[6]; d_qp[slot*3+2] = p[7];
    }

    if (b == 0 && c == 0 && s_tot < KK) {
        __syncthreads();
        bool neg = !pos;
        unsigned bal2 = __ballot_sync(0xffffffffu, neg);
        int wpre2 = __popc(bal2 & ((1u << lane) - 1u));
        __shared__ int wcnt2[8], woff2[8];
        if (lane == 0) wcnt2[wid] = __popc(bal2);
        __syncthreads();
        if (tid == 0) {
            int a = 0;
#pragma unroll
            for (int w = 0; w < 8; w++) { woff2[w] = a; a += wcnt2[w]; }
        }
        __syncthreads();
        int totneg = woff2[7] + wcnt2[7];
        int nrank = s_tot + woff2[wid] + wpre2;
        __shared__ int nd[256], nslot[256];
        __shared__ unsigned char nct[256];
        if (neg && nrank < KK) {
            int li = woff2[wid] + wpre2;
            nd[li] = d; nslot[li] = nrank; nct[li] = ct;
        }
        __syncthreads();
        int mn = totneg;
        {
            int cap = KK - s_tot; if (cap < 0) cap = 0;
            if (mn > cap) mn = cap;
        }
        for (int i = tid; i < mn*LL; i += 256) {
            int p = i >> 5, l = i & 31;
            d_emb[nslot[p]*LL + l] = line[(size_t)nd[p]*(size_t)LL + l];
        }
        if (tid < mn) {
            int slot = nslot[tid];
            unsigned char cc = nct[tid];
            d_lab[slot] = cc & 31;
            d_val[slot] = 0;
            int t = cc >> 5;
            const float* p = tgt + (size_t)t*9;
            d_qp[slot*3+0] = p[5]; d_qp[slot*3+1] = p[6]; d_qp[slot*3+2] = p[7];
        }
    }
}

// Fused pairwise + triplet. Block i (anchor), thread j (partner). Partials per block.
__global__ void k_pairstrip() {
    int i = blockIdx.x, j = threadIdx.x;
    __shared__ float ei[LL], ni[LL], qi[3];
    __shared__ int labi, vali;
    __shared__ float sdist[KK];
    __shared__ unsigned pm[8], nm[8];

    if (j < LL) ei[j] = d_emb[i*LL + j];
    if (j == 0) {
        labi = d_lab[i]; vali = d_val[i];
        qi[0] = d_qp[i*3+0]; qi[1] = d_qp[i*3+1]; qi[2] = d_qp[i*3+2];
    }
    __syncthreads();
    if (j == 0) {
        float s = 0.0f;
        for (int l = 0; l < LL; l++) s += ei[l]*ei[l];
        float n = fmaxf(sqrtf(s), 1e-12f);
        for (int l = 0; l < LL; l++) ni[l] = ei[l] / n;
    }
    __syncthreads();

    float ej[LL];
#pragma unroll
    for (int l = 0; l < LL; l++) ej[l] = d_emb[j*LL + l];
    float s = 0.0f;
#pragma unroll
    for (int l = 0; l < LL; l++) s += ej[l]*ej[l];
    float rnj = 1.0f / fmaxf(sqrtf(s), 1e-12f);

    float sq = 0.0f, esq = 0.0f;
#pragma unroll
    for (int l = 0; l < LL; l++) {
        float dn = ni[l] - ej[l]*rnj; sq  += dn*dn;
        float de = ei[l] - ej[l];     esq += de*de;
    }
    float dist = sqrtf(fmaxf(sq, 1e-12f));
    sdist[j] = dist;

    float qsq = 0.0f;
#pragma unroll
    for (int c = 0; c < 3; c++) { float dq = qi[c] - d_qp[j*3+c]; qsq += dq*dq; }

    bool vp   = vali && d_val[j] && (i != j);
    bool same = (labi == d_lab[j]);
    bool pp = vp &&  same && (dist > 0.2f);
    bool np = vp && !same && (dist < 0.8f);

    unsigned pb = __ballot_sync(0xffffffffu, pp);
    unsigned nb = __ballot_sync(0xffffffffu, np);
    if ((j & 31) == 0) { pm[j>>5] = pb; nm[j>>5] = nb; }

    double dk = pp ? (double)((esq - qsq) * (esq - qsq)) : 0.0;
    int cp = pp ? 1 : 0, cn = np ? 1 : 0;
#pragma unroll
    for (int st = 16; st > 0; st >>= 1) {
        dk += __shfl_down_sync(0xffffffffu, dk, st);
        cp += __shfl_down_sync(0xffffffffu, cp, st);
        cn += __shfl_down_sync(0xffffffffu, cn, st);
    }
    __shared__ double wdk[8];
    __shared__ int wcp[8], wcn[8];
    int wid = j >> 5, lane = j & 31;
    if (lane == 0) { wdk[wid] = dk; wcp[wid] = cp; wcn[wid] = cn; }
    __syncthreads();
    if (j == 0) {
        double t = 0.0; int p = 0, n = 0;
        for (int w = 0; w < 8; w++) { t += wdk[w]; p += wcp[w]; n += wcn[w]; }
        d_pdesk[i] = t; d_pnpp[i] = p; d_pnnp[i] = n;
    }

    __shared__ int pj[KK];
    __shared__ int npj;
    if (j == 0) {
        int n = 0;
        for (int w = 0; w < 8; w++) {
            unsigned m = pm[w];
            while (m) { int bp = __ffs(m) - 1; pj[n++] = w*32 + bp; m &= (m - 1); }
        }
        npj = n;
    }
    __syncthreads();
    int n = npj;
    if (n == 0) {
        if (j == 0) { d_ptrips[i] = 0.0; d_ptc[i] = 0; }
        return;
    }

    bool isneg = (nm[j >> 5] >> (j & 31)) & 1u;
    double ls = 0.0;
    int lc = 0;
    if (isneg) {
        float dk2 = sdist[j];
        for (int a = 0; a < n; a++) {
            float l = sdist[pj[a]] - dk2 + 0.2f;
            if (l > 0.0f) { ls += (double)l; lc++; }
        }
    }
#pragma unroll
    for (int st = 16; st > 0; st >>= 1) {
        ls += __shfl_down_sync(0xffffffffu, ls, st);
        lc += __shfl_down_sync(0xffffffffu, lc, st);
    }
    __shared__ double wls[8];
    __shared__ int wlc[8];
    if (lane == 0) { wls[wid] = ls; wlc[wid] = lc; }
    __syncthreads();
    if (j == 0) {
        double t = 0.0; int c = 0;
        for (int w = 0; w < 8; w++) { t += wls[w]; c += wlc[w]; }
        d_ptrips[i] = t; d_ptc[i] = c;
    }
}

// Reduce all partials, compute final 5 outputs.
__global__ void k_final(float* __restrict__ out) {
    const int tid = threadIdx.x;
    double ll = 0.0, lp = 0.0, ce = 0.0;
    int np = 0;
    for (int i = tid; i < BB*NCE; i += 256) {
        ll += d_pll[i]; lp += d_plp[i]; ce += d_pce[i]; np += d_npb[i];
    }
    double dsk = 0.0, trp = 0.0;
    int npp = 0, nnp = 0, tc = 0;
    for (int i = tid; i < KK; i += 256) {
        dsk += d_pdesk[i]; trp += d_ptrips[i];
        npp += d_pnpp[i]; nnp += d_pnnp[i]; tc += d_ptc[i];
    }
    if (tid < BB) ce += d_topksum[tid];

#pragma unroll
    for (int s = 16; s > 0; s >>= 1) {
        ll += __shfl_down_sync(0xffffffffu, ll, s);
        lp += __shfl_down_sync(0xffffffffu, lp, s);
        ce += __shfl_down_sync(0xffffffffu, ce, s);
        np += __shfl_down_sync(0xffffffffu, np, s);
        dsk += __shfl_down_sync(0xffffffffu, dsk, s);
        trp += __shfl_down_sync(0xffffffffu, trp, s);
        npp += __shfl_down_sync(0xffffffffu, npp, s);
        nnp += __shfl_down_sync(0xffffffffu, nnp, s);
        tc  += __shfl_down_sync(0xffffffffu, tc, s);
    }
    __shared__ double sll[8], slp[8], sce2[8], sdsk[8], strp[8];
    __shared__ int snp[8], snpp[8], snnp[8], stc[8];
    int wid = tid >> 5, lane = tid & 31;
    if (lane == 0) {
        sll[wid] = ll; slp[wid] = lp; sce2[wid] = ce; snp[wid] = np;
        sdsk[wid] = dsk; strp[wid] = trp; snpp[wid] = npp; snnp[wid] = nnp; stc[wid] = tc;
    }
    __syncthreads();
    if (tid == 0) {
        for (int w = 1; w < 8; w++) {
            sll[0] += sll[w]; slp[0] += slp[w]; sce2[0] += sce2[w]; snp[0] += snp[w];
            sdsk[0] += sdsk[w]; strp[0] += strp[w];
            snpp[0] += snpp[w]; snnp[0] += snnp[w]; stc[0] += stc[w];
        }
        double N = (double)snp[0];
        if (N < 1.0) N = 1.0;
        double lossl = sll[0] / N;
        double lossc = sce2[0] / N;
        double lossp = slp[0] / N;

        double dnpp = (snpp[0] < 1) ? 1.0 : (double)snpp[0];
        double losst = strp[0] / (double)((stc[0] < 1) ? 1 : stc[0]);
        long long pn = (long long)snpp[0] + (long long)snnp[0];
        double dpn = (pn < 1) ? 1.0 : (double)pn;

        double ldesk = sdsk[0] / dnpp + losst / dpn;
        ldesk = ldesk / dnpp / 32.0;

        out[0] = (float)lossl;
        out[1] = (float)lossc;
        out[2] = (float)lossp;
        out[3] = (float)ldesk;
        out[4] = (float)losst;
    }
}

// ---------------- host launcher ----------------
extern "C" void kernel_launch(void* const* d_in, const int* in_sizes, int n_in,
                              void* d_out, int out_size) {
    const float *loc = 0, *conf = 0, *line = 0, *pose = 0, *dbox = 0, *tgt = 0;
    for (int i = 0; i < n_in; i++) {
        switch (in_sizes[i]) {
            case BB*DD*4:  loc  = (const float*)d_in[i]; break;
            case BB*DD*CC: conf = (const float*)d_in[i]; break;
            case BB*DD*LL: line = (const float*)d_in[i]; break;
            case BB*DD*3:  pose = (const float*)d_in[i]; break;
            case DD*4:     dbox = (const float*)d_in[i]; break;
            case BB*OO*9:  tgt  = (const float*)d_in[i]; break;
            default: break;
        }
    }
    if (!loc)  loc  = (const float*)d_in[0];
    if (!conf) conf = (const float*)d_in[1];
    if (!line) line = (const float*)d_in[2];
    if (!pose) pose = (const float*)d_in[3];
    if (!dbox) dbox = (const float*)d_in[4];
    if (!tgt)  tgt  = (const float*)d_in[5];

    // Created once (first, non-captured call); reused on every call thereafter.
    static cudaStream_t s2 = [](){
        cudaStream_t s; cudaStreamCreateWithFlags(&s, cudaStreamNonBlocking); return s;
    }();
    static cudaEvent_t evFork = [](){
        cudaEvent_t e; cudaEventCreateWithFlags(&e, cudaEventDisableTiming); return e;
    }();
    static cudaEvent_t evJoin = [](){
        cudaEvent_t e; cudaEventCreateWithFlags(&e, cudaEventDisableTiming); return e;
    }();

    k_match1<<<dim3(NCH, BB), 256>>>(dbox, tgt);
    k_encce<<<dim3(NCE, BB), 256>>>(loc, pose, dbox, tgt, conf);

    // fork: topk runs concurrently with compact+pairstrip
    cudaEventRecord(evFork, 0);
    cudaStreamWaitEvent(s2, evFork, 0);
    k_topk<<<BB, 1024, 0, s2>>>();

    k_compact<<<dim3(NCE, BB), 256>>>(line, tgt);
    k_pairstrip<<<KK, 256>>>();

    // join
    cudaEventRecord(evJoin, s2);
    cudaStreamWaitEvent(0, evJoin, 0);
    k_final<<<1, 256>>>((float*)d_out);
}